// round 13
// baseline (speedup 1.0000x reference)
#include <cuda_runtime.h>
#include <cuda_bf16.h>
#include <cstdint>

// ---------------- static scratch (no runtime allocation allowed) ----------------
#define MAXN 100000
#define MAXE 1200000

__device__ __nv_bfloat16  g_actb[(size_t)MAXN * 128];   // layer outputs h1(64)/h2(128), bf16
__device__ __nv_bfloat16  g_bufY[(size_t)MAXN * 128];   // aggregated features (bf16)
__device__ __nv_bfloat16  g_featb[(size_t)MAXN * 64];   // bf16 copy of input features
__device__ float2 g_dc[MAXN];                  // (weighted degree, count)
__device__ float  g_dinv[MAXN];                // d^{-1/2}
__device__ int    g_rowptr[MAXN + 1];
__device__ int    g_woff[MAXN + 1];
__device__ int    g_bsums[128];
__device__ int2   g_csr[MAXE];                 // packed (src, norm)
__device__ int    g_segstart[257];
__device__ __nv_bfloat16 g_whiT[45056];        // bf16-hi of W1|W2|W3, TRANSPOSED [OUT][K]
__device__ __nv_bfloat16 g_wloT[45056];        // bf16 residual, transposed
__device__ float g_poolc[256 * 256];           // conv3 segment sums (fp32, atomically built)
__device__ float g_poolf[256 * 64];            // feature segment sums
__device__ float g_fc1[256 * 1024];

// ---------------- helpers ----------------
__device__ __forceinline__ void bf8_to_f8(uint4 v, float* f) {
    const __nv_bfloat162* p = reinterpret_cast<const __nv_bfloat162*>(&v);
    #pragma unroll
    for (int j = 0; j < 4; j++) {
        float2 t = __bfloat1622float2(p[j]);
        f[2 * j] = t.x; f[2 * j + 1] = t.y;
    }
}

__device__ __forceinline__ void cp_async16(void* smem, const void* gmem, int src_bytes) {
    uint32_t s = (uint32_t)__cvta_generic_to_shared(smem);
    asm volatile("cp.async.cg.shared.global [%0], [%1], 16, %2;" :: "r"(s), "l"(gmem), "r"(src_bytes));
}
#define CP_COMMIT asm volatile("cp.async.commit_group;")

// ---------------- fused prep: wsplit | featcvt | seg_bounds | deg_init | zero poolc ----------------
__global__ void prep_kernel(const float* __restrict__ W1, const float* __restrict__ W2,
                            const float* __restrict__ W3, __nv_bfloat16* __restrict__ hi,
                            __nv_bfloat16* __restrict__ lo,
                            const float* __restrict__ feature, __nv_bfloat16* __restrict__ featb,
                            const int* __restrict__ pb, int* __restrict__ segstart,
                            float2* __restrict__ dc, float* __restrict__ poolc,
                            int N, int nWS, int nFC, int nDI) {
    int b = blockIdx.x, t = threadIdx.x;
    if (b < nWS) {
        int i = b * 256 + t;
        if (i < 45056) {
            float w; int o;
            if (i < 4096)       { int k = i >> 6, n = i & 63;  w = W1[i];          o = n * 64 + k; }
            else if (i < 12288) { int j = i - 4096;  int k = j >> 7, n = j & 127; w = W2[j]; o = 4096  + n * 64  + k; }
            else                { int j = i - 12288; int k = j >> 8, n = j & 255; w = W3[j]; o = 12288 + n * 128 + k; }
            __nv_bfloat16 h = __float2bfloat16(w);
            hi[o] = h;
            lo[o] = __float2bfloat16(w - __bfloat162float(h));
        }
    } else if (b < nWS + nFC) {
        int i = (b - nWS) * 256 + t;
        if (i < N * 16) {
            float4 v = reinterpret_cast<const float4*>(feature)[i];
            __nv_bfloat162* o = reinterpret_cast<__nv_bfloat162*>(featb) + i * 2;
            o[0] = __floats2bfloat162_rn(v.x, v.y);
            o[1] = __floats2bfloat162_rn(v.z, v.w);
        }
    } else if (b < nWS + nFC + 2) {
        int s = (b - nWS - nFC) * 256 + t;
        if (s <= 256) {
            int lo2 = 0, hi2 = N;
            while (lo2 < hi2) {
                int mid = (lo2 + hi2) >> 1;
                if (pb[mid] < s) lo2 = mid + 1; else hi2 = mid;
            }
            segstart[s] = lo2;
        }
    } else if (b < nWS + nFC + 2 + nDI) {
        int i = (b - nWS - nFC - 2) * 256 + t;
        if (i < N) dc[i] = make_float2(1.0f, 0.0f);   // self-loop weight
    } else {
        int i = (b - nWS - nFC - 2 - nDI) * 256 + t;
        if (i < 256 * 256) poolc[i] = 0.0f;
    }
}

__global__ void deg_acc_kernel(const int* __restrict__ dst, const float* __restrict__ w,
                               float2* __restrict__ dc, int E) {
    int e = blockIdx.x * blockDim.x + threadIdx.x;
    if (e < E) atomicAdd(&dc[dst[e]], make_float2(w[e], 1.0f));
}

// ---------------- scan: cnt -> rowptr (exclusive); dinv folded in ----------------
__global__ void scan_block_kernel(const float2* __restrict__ dc, int* __restrict__ rowptr,
                                  int* __restrict__ bsums, float* __restrict__ dinv, int N) {
    __shared__ int sh[1024];
    int i = blockIdx.x * 1024 + threadIdx.x;
    int v = 0;
    if (i < N) {
        float2 d = dc[i];
        v = (int)(d.y + 0.5f);
        dinv[i] = rsqrtf(d.x);            // deg >= 1 (self-loop)
    }
    sh[threadIdx.x] = v;
    __syncthreads();
    for (int off = 1; off < 1024; off <<= 1) {
        int t = (threadIdx.x >= off) ? sh[threadIdx.x - off] : 0;
        __syncthreads();
        sh[threadIdx.x] += t;
        __syncthreads();
    }
    if (i < N) rowptr[i] = sh[threadIdx.x] - v;
    if (threadIdx.x == 1023) bsums[blockIdx.x] = sh[1023];
}

__global__ void scan_sums_kernel(int* bsums, int nb) {
    __shared__ int sh[128];
    int v = (threadIdx.x < nb) ? bsums[threadIdx.x] : 0;
    sh[threadIdx.x] = v;
    __syncthreads();
    for (int off = 1; off < 128; off <<= 1) {
        int t = (threadIdx.x >= off) ? sh[threadIdx.x - off] : 0;
        __syncthreads();
        sh[threadIdx.x] += t;
        __syncthreads();
    }
    if (threadIdx.x < nb) bsums[threadIdx.x] = sh[threadIdx.x] - v;
}

__global__ void add_off_kernel(int* __restrict__ rowptr, const int* __restrict__ bsums,
                               int* __restrict__ woff, int N, int E) {
    int i = blockIdx.x * blockDim.x + threadIdx.x;
    if (i < N) {
        int r = rowptr[i] + bsums[i >> 10];
        rowptr[i] = r;
        woff[i] = r;
    }
    if (i == N) rowptr[N] = E;
}

__global__ void place_kernel(const int* __restrict__ src, const int* __restrict__ dst,
                             const float* __restrict__ w, const float* __restrict__ dinv,
                             int* __restrict__ woff, int2* __restrict__ csr, int E) {
    int e = blockIdx.x * blockDim.x + threadIdx.x;
    if (e >= E) return;
    int s = src[e], d = dst[e];
    float nr = dinv[s] * w[e] * dinv[d];
    int pos = atomicAdd(&woff[d], 1);
    csr[pos] = make_int2(s, __float_as_int(nr));
}

// ---------------- CSR gather aggregation (bf16 in/out, fp32 accumulate) ----------------
template<int IN>
__global__ void gather_kernel(const int* __restrict__ rowptr, const int2* __restrict__ csr,
                              const __nv_bfloat16* __restrict__ X, const float* __restrict__ dinv,
                              __nv_bfloat16* __restrict__ Y, int N) {
    const int G = IN / 8;                 // threads per node (8 bf16 = 16B each)
    const int NPB = 256 / G;
    int lane = threadIdx.x % G;
    int node = blockIdx.x * NPB + threadIdx.x / G;
    if (node >= N) return;

    int beg = rowptr[node];
    int end = rowptr[node + 1];
    float di = dinv[node];
    float sl = di * di;

    float acc[8];
    {
        uint4 xv = *reinterpret_cast<const uint4*>(&X[(size_t)node * IN + lane * 8]);
        float xf[8]; bf8_to_f8(xv, xf);
        #pragma unroll
        for (int j = 0; j < 8; j++) acc[j] = sl * xf[j];
    }

    int k = beg;
    for (; k + 4 <= end; k += 4) {
        int2 p0 = csr[k], p1 = csr[k + 1], p2 = csr[k + 2], p3 = csr[k + 3];
        uint4 v0 = *reinterpret_cast<const uint4*>(&X[(size_t)p0.x * IN + lane * 8]);
        uint4 v1 = *reinterpret_cast<const uint4*>(&X[(size_t)p1.x * IN + lane * 8]);
        uint4 v2 = *reinterpret_cast<const uint4*>(&X[(size_t)p2.x * IN + lane * 8]);
        uint4 v3 = *reinterpret_cast<const uint4*>(&X[(size_t)p3.x * IN + lane * 8]);
        float n0 = __int_as_float(p0.y), n1 = __int_as_float(p1.y);
        float n2 = __int_as_float(p2.y), n3 = __int_as_float(p3.y);
        float f0[8], f1[8], f2[8], f3[8];
        bf8_to_f8(v0, f0); bf8_to_f8(v1, f1); bf8_to_f8(v2, f2); bf8_to_f8(v3, f3);
        #pragma unroll
        for (int j = 0; j < 8; j++)
            acc[j] += n0 * f0[j] + n1 * f1[j] + n2 * f2[j] + n3 * f3[j];
    }
    for (; k < end; k++) {
        int2 p0 = csr[k];
        float n0 = __int_as_float(p0.y);
        uint4 v0 = *reinterpret_cast<const uint4*>(&X[(size_t)p0.x * IN + lane * 8]);
        float f0[8]; bf8_to_f8(v0, f0);
        #pragma unroll
        for (int j = 0; j < 8; j++) acc[j] += n0 * f0[j];
    }

    uint4 o;
    __nv_bfloat162* q = reinterpret_cast<__nv_bfloat162*>(&o);
    #pragma unroll
    for (int j = 0; j < 4; j++) q[j] = __floats2bfloat162_rn(acc[2 * j], acc[2 * j + 1]);
    *reinterpret_cast<uint4*>(&Y[(size_t)node * IN + lane * 8]) = o;
}

// ---------------- bf16 tensor-core GEMM, cp.async double-buffered ----------------
// H = relu(A @ (Whi + Wlo) + bias). POOL=false: bf16 store. POOL=true: no store —
// fp32 results accumulated per-segment into poolc (pb sorted -> block spans few segs).
template<int OUT, int K, bool POOL>
__global__ void __launch_bounds__(256) bf16_gemm_kernel(
    const __nv_bfloat16* __restrict__ A, const __nv_bfloat16* __restrict__ BhiT,
    const __nv_bfloat16* __restrict__ BloT, const float* __restrict__ bias,
    __nv_bfloat16* __restrict__ Cout, const int* __restrict__ pb,
    float* __restrict__ poolc, int N)
{
    constexpr int NITER = K / 32;
    __shared__ __align__(16) __nv_bfloat16 As[2][128][40];
    __shared__ __align__(16) __nv_bfloat16 Bh[2][64][40];
    __shared__ __align__(16) __nv_bfloat16 Bl[2][64][40];

    int t = threadIdx.x;
    int lane = t & 31, w = t >> 5;
    int warpM = w & 3, warpN = w >> 2;
    int g = lane >> 2, tc = lane & 3;
    int rowBase = blockIdx.x * 128;
    int colBase = blockIdx.y * 64;

    int am0 = t >> 2, akq = (t & 3) * 8;
    int am1 = am0 + 64;
    int bn = t >> 2, bkq = (t & 3) * 8;

    auto load_tile = [&](int kb, int buf) {
        const __nv_bfloat16* a0 = &A[(size_t)(rowBase + am0) * K + kb + akq];
        const __nv_bfloat16* a1 = &A[(size_t)(rowBase + am1) * K + kb + akq];
        cp_async16(&As[buf][am0][akq], (rowBase + am0 < N) ? a0 : A, (rowBase + am0 < N) ? 16 : 0);
        cp_async16(&As[buf][am1][akq], (rowBase + am1 < N) ? a1 : A, (rowBase + am1 < N) ? 16 : 0);
        cp_async16(&Bh[buf][bn][bkq], &BhiT[(size_t)(colBase + bn) * K + kb + bkq], 16);
        cp_async16(&Bl[buf][bn][bkq], &BloT[(size_t)(colBase + bn) * K + kb + bkq], 16);
    };

    float acc[2][4][4];
    #pragma unroll
    for (int a = 0; a < 2; a++)
        #pragma unroll
        for (int b = 0; b < 4; b++)
            #pragma unroll
            for (int c = 0; c < 4; c++) acc[a][b][c] = 0.0f;

    load_tile(0, 0);
    CP_COMMIT;

    #pragma unroll
    for (int it = 0; it < NITER; it++) {
        if (it + 1 < NITER) {
            load_tile((it + 1) * 32, (it + 1) & 1);
            CP_COMMIT;
            asm volatile("cp.async.wait_group 1;");
        } else {
            asm volatile("cp.async.wait_group 0;");
        }
        __syncthreads();
        int buf = it & 1;

        #pragma unroll
        for (int ks = 0; ks < 32; ks += 16) {
            uint32_t af[2][4];
            #pragma unroll
            for (int mt = 0; mt < 2; mt++) {
                int m0 = warpM * 32 + mt * 16 + g;
                af[mt][0] = *reinterpret_cast<const uint32_t*>(&As[buf][m0][ks + tc * 2]);
                af[mt][1] = *reinterpret_cast<const uint32_t*>(&As[buf][m0 + 8][ks + tc * 2]);
                af[mt][2] = *reinterpret_cast<const uint32_t*>(&As[buf][m0][ks + tc * 2 + 8]);
                af[mt][3] = *reinterpret_cast<const uint32_t*>(&As[buf][m0 + 8][ks + tc * 2 + 8]);
            }
            #pragma unroll
            for (int nt = 0; nt < 4; nt++) {
                int n0 = warpN * 32 + nt * 8 + g;
                uint32_t bh0 = *reinterpret_cast<const uint32_t*>(&Bh[buf][n0][ks + tc * 2]);
                uint32_t bh1 = *reinterpret_cast<const uint32_t*>(&Bh[buf][n0][ks + tc * 2 + 8]);
                uint32_t bl0 = *reinterpret_cast<const uint32_t*>(&Bl[buf][n0][ks + tc * 2]);
                uint32_t bl1 = *reinterpret_cast<const uint32_t*>(&Bl[buf][n0][ks + tc * 2 + 8]);
                #pragma unroll
                for (int mt = 0; mt < 2; mt++) {
                    float* c = acc[mt][nt];
                    asm volatile(
                        "mma.sync.aligned.m16n8k16.row.col.f32.bf16.bf16.f32 "
                        "{%0,%1,%2,%3}, {%4,%5,%6,%7}, {%8,%9}, {%0,%1,%2,%3};"
                        : "+f"(c[0]), "+f"(c[1]), "+f"(c[2]), "+f"(c[3])
                        : "r"(af[mt][0]), "r"(af[mt][1]), "r"(af[mt][2]), "r"(af[mt][3]),
                          "r"(bh0), "r"(bh1));
                    asm volatile(
                        "mma.sync.aligned.m16n8k16.row.col.f32.bf16.bf16.f32 "
                        "{%0,%1,%2,%3}, {%4,%5,%6,%7}, {%8,%9}, {%0,%1,%2,%3};"
                        : "+f"(c[0]), "+f"(c[1]), "+f"(c[2]), "+f"(c[3])
                        : "r"(af[mt][0]), "r"(af[mt][1]), "r"(af[mt][2]), "r"(af[mt][3]),
                          "r"(bl0), "r"(bl1));
                }
            }
        }
        __syncthreads();
    }

    if (!POOL) {
        // epilogue: bias + relu, bf16 out
        #pragma unroll
        for (int mt = 0; mt < 2; mt++) {
            #pragma unroll
            for (int nt = 0; nt < 4; nt++) {
                int row = rowBase + warpM * 32 + mt * 16 + g;
                int col = colBase + warpN * 32 + nt * 8 + tc * 2;
                float b0 = bias[col], b1 = bias[col + 1];
                float* c = acc[mt][nt];
                if (row < N)
                    *reinterpret_cast<__nv_bfloat162*>(&Cout[(size_t)row * OUT + col]) =
                        __floats2bfloat162_rn(fmaxf(c[0] + b0, 0.f), fmaxf(c[1] + b1, 0.f));
                if (row + 8 < N)
                    *reinterpret_cast<__nv_bfloat162*>(&Cout[(size_t)(row + 8) * OUT + col]) =
                        __floats2bfloat162_rn(fmaxf(c[2] + b0, 0.f), fmaxf(c[3] + b1, 0.f));
            }
        }
    } else {
        // epilogue: bias + relu, accumulate fp32 segment sums (h3 never materialized)
        __shared__ float psum[8][64];
        __shared__ int s_bounds[2];
        for (int lin = t; lin < 512; lin += 256) (&psum[0][0])[lin] = 0.0f;
        if (t == 0) {
            s_bounds[0] = pb[min(rowBase, N - 1)];
            s_bounds[1] = pb[min(rowBase + 127, N - 1)];
        }
        __syncthreads();
        int seg_lo = s_bounds[0];
        bool fits = (s_bounds[1] - seg_lo) < 8;

        #pragma unroll
        for (int mt = 0; mt < 2; mt++) {
            #pragma unroll
            for (int nt = 0; nt < 4; nt++) {
                int row = rowBase + warpM * 32 + mt * 16 + g;
                int cl = warpN * 32 + nt * 8 + tc * 2;
                float b0 = bias[colBase + cl], b1 = bias[colBase + cl + 1];
                float* c = acc[mt][nt];
                #pragma unroll
                for (int h = 0; h < 2; h++) {
                    int r = row + h * 8;
                    if (r < N) {
                        float v0 = fmaxf(c[2 * h] + b0, 0.f);
                        float v1 = fmaxf(c[2 * h + 1] + b1, 0.f);
                        int sg = pb[r];
                        if (fits) {
                            if (v0 != 0.f) atomicAdd(&psum[sg - seg_lo][cl], v0);
                            if (v1 != 0.f) atomicAdd(&psum[sg - seg_lo][cl + 1], v1);
                        } else {
                            if (v0 != 0.f) atomicAdd(&poolc[sg * 256 + colBase + cl], v0);
                            if (v1 != 0.f) atomicAdd(&poolc[sg * 256 + colBase + cl + 1], v1);
                        }
                    }
                }
            }
        }
        __syncthreads();
        if (fits) {
            int nseg = s_bounds[1] - seg_lo + 1;
            for (int lin = t; lin < nseg * 64; lin += 256) {
                int s = lin >> 6, cc = lin & 63;
                float v = psum[s][cc];
                if (v != 0.f) atomicAdd(&poolc[(seg_lo + s) * 256 + colBase + cc], v);
            }
        }
    }
}

// ---------------- feature pooling: per-segment fp32 sums ----------------
// one block per segment; 256 threads = 16 float4-col-groups x 16 node-ways
__global__ void featpool_kernel(const float* __restrict__ feature,
                                const int* __restrict__ segstart, float* __restrict__ poolf) {
    __shared__ float4 sh[16][16];
    int seg = blockIdx.x;
    int c = threadIdx.x % 16;
    int r = threadIdx.x / 16;
    int beg = segstart[seg], end = segstart[seg + 1];

    float4 acc = make_float4(0.f, 0.f, 0.f, 0.f);
    for (int i = beg + r; i < end; i += 16) {
        float4 v = *reinterpret_cast<const float4*>(&feature[(size_t)i * 64 + c * 4]);
        acc.x += v.x; acc.y += v.y; acc.z += v.z; acc.w += v.w;
    }
    sh[r][c] = acc;
    __syncthreads();
    for (int s = 8; s > 0; s >>= 1) {
        if (r < s) {
            float4 a = sh[r][c], b = sh[r + s][c];
            sh[r][c] = make_float4(a.x + b.x, a.y + b.y, a.z + b.z, a.w + b.w);
        }
        __syncthreads();
    }
    if (r == 0)
        *reinterpret_cast<float4*>(&poolf[seg * 64 + c * 4]) = sh[0][c];
}

// ---------------- MLP head ----------------
__global__ void fc1_kernel(const float* __restrict__ poolc, const float* __restrict__ poolf,
                           const int* __restrict__ segstart,
                           const float* __restrict__ Wf1, const float* __restrict__ bf1,
                           float* __restrict__ fc1) {
    __shared__ float srow[8][320];
    __shared__ float sinv[8];
    int rowBase = blockIdx.y * 8;
    int col = blockIdx.x * 256 + threadIdx.x;

    for (int lin = threadIdx.x; lin < 8 * 320; lin += 256) {
        int rr = lin / 320, k = lin % 320;
        int row = rowBase + rr;
        srow[rr][k] = (k < 256) ? poolc[row * 256 + k] : poolf[row * 64 + (k - 256)];
    }
    if (threadIdx.x < 8) {
        int row = rowBase + threadIdx.x;
        int c = segstart[row + 1] - segstart[row];
        sinv[threadIdx.x] = 1.0f / fmaxf((float)c, 1.0f);
    }
    __syncthreads();

    float acc[8] = {};
    #pragma unroll 4
    for (int k = 0; k < 320; k++) {
        float wv = Wf1[(size_t)k * 1024 + col];
        #pragma unroll
        for (int rr = 0; rr < 8; rr++) acc[rr] += srow[rr][k] * wv;
    }
    float b = bf1[col];
    #pragma unroll
    for (int rr = 0; rr < 8; rr++) {
        float v = acc[rr] * sinv[rr] + b;
        fc1[(size_t)(rowBase + rr) * 1024 + col] = fmaxf(v, 0.f);
    }
}

__global__ void fc2_kernel(const float* __restrict__ fc1, const float* __restrict__ Wf2,
                           const float* __restrict__ bf2, float* __restrict__ out) {
    int row = blockIdx.x;
    float a = 0.f;
    for (int j = threadIdx.x; j < 1024; j += 256)
        a += fc1[(size_t)row * 1024 + j] * Wf2[j];
    __shared__ float red[256];
    red[threadIdx.x] = a;
    __syncthreads();
    for (int s = 128; s > 0; s >>= 1) {
        if (threadIdx.x < s) red[threadIdx.x] += red[threadIdx.x + s];
        __syncthreads();
    }
    if (threadIdx.x == 0) out[row] = red[0] + bf2[0];
}

// ---------------- launch ----------------
extern "C" void kernel_launch(void* const* d_in, const int* in_sizes, int n_in,
                              void* d_out, int out_size) {
    const float* feature = (const float*)d_in[0];
    const int*   ei      = (const int*)d_in[1];
    const float* weight  = (const float*)d_in[2];
    const int*   pb      = (const int*)d_in[3];
    const float* W1 = (const float*)d_in[4];  const float* b1  = (const float*)d_in[5];
    const float* W2 = (const float*)d_in[6];  const float* b2  = (const float*)d_in[7];
    const float* W3 = (const float*)d_in[8];  const float* b3  = (const float*)d_in[9];
    const float* Wf1 = (const float*)d_in[10]; const float* bf1 = (const float*)d_in[11];
    const float* Wf2 = (const float*)d_in[12]; const float* bf2 = (const float*)d_in[13];
    float* out = (float*)d_out;

    int N = in_sizes[0] / 64;
    int E = in_sizes[2];
    const int* src = ei;
    const int* dst = ei + E;

    float *dinv, *poolc, *poolf, *fc1;
    __nv_bfloat16 *actb, *bufY, *featb, *whiT, *wloT;
    float2 *dc;
    int *rowptr, *woff, *bsums, *segstart;
    int2 *csr;
    cudaGetSymbolAddress((void**)&actb, g_actb);
    cudaGetSymbolAddress((void**)&bufY, g_bufY);
    cudaGetSymbolAddress((void**)&featb, g_featb);
    cudaGetSymbolAddress((void**)&dc, g_dc);
    cudaGetSymbolAddress((void**)&dinv, g_dinv);
    cudaGetSymbolAddress((void**)&rowptr, g_rowptr);
    cudaGetSymbolAddress((void**)&woff, g_woff);
    cudaGetSymbolAddress((void**)&bsums, g_bsums);
    cudaGetSymbolAddress((void**)&csr, g_csr);
    cudaGetSymbolAddress((void**)&segstart, g_segstart);
    cudaGetSymbolAddress((void**)&whiT, g_whiT);
    cudaGetSymbolAddress((void**)&wloT, g_wloT);
    cudaGetSymbolAddress((void**)&poolc, g_poolc);
    cudaGetSymbolAddress((void**)&poolf, g_poolf);
    cudaGetSymbolAddress((void**)&fc1,  g_fc1);

    const int T = 256;
    int nb = (N + 1023) / 1024;
    int nWS = (45056 + 255) / 256;
    int nFC = (N * 16 + 255) / 256;
    int nDI = (N + 255) / 256;
    int nPZ = 256;   // zero 256*256 poolc

    // fused prep
    prep_kernel<<<nWS + nFC + 2 + nDI + nPZ, T>>>(W1, W2, W3, whiT, wloT, feature, featb,
                                                  pb, segstart, dc, poolc, N, nWS, nFC, nDI);
    deg_acc_kernel<<<(E + T - 1) / T, T>>>(dst, weight, dc, E);
    scan_block_kernel<<<nb, 1024>>>(dc, rowptr, bsums, dinv, N);
    scan_sums_kernel<<<1, 128>>>(bsums, nb);
    add_off_kernel<<<(N + 1 + T - 1) / T, T>>>(rowptr, bsums, woff, N, E);
    place_kernel<<<(E + T - 1) / T, T>>>(src, dst, weight, dinv, woff, csr, E);

    int gb128 = (N + 127) / 128;

    // layer 1: [N,64] -> [N,64]
    gather_kernel<64><<<(N * 8 + 255) / 256, 256>>>(rowptr, csr, featb, dinv, bufY, N);
    bf16_gemm_kernel<64, 64, false><<<dim3(gb128, 1), 256>>>(bufY, whiT, wloT, b1, actb, nullptr, nullptr, N);

    // layer 2: [N,64] -> [N,128]
    gather_kernel<64><<<(N * 8 + 255) / 256, 256>>>(rowptr, csr, actb, dinv, bufY, N);
    bf16_gemm_kernel<128, 64, false><<<dim3(gb128, 2), 256>>>(bufY, whiT + 4096, wloT + 4096, b2, actb, nullptr, nullptr, N);

    // layer 3: [N,128] -> pooled segment sums directly (h3 never stored)
    gather_kernel<128><<<(N * 16 + 255) / 256, 256>>>(rowptr, csr, actb, dinv, bufY, N);
    bf16_gemm_kernel<256, 128, true><<<dim3(gb128, 4), 256>>>(bufY, whiT + 12288, wloT + 12288, b3, nullptr, pb, poolc, N);

    // feature pooling (fp32 source) + MLP head
    featpool_kernel<<<256, 256>>>(feature, segstart, poolf);
    fc1_kernel<<<dim3(4, 32), 256>>>(poolc, poolf, segstart, Wf1, bf1, fc1);
    fc2_kernel<<<256, 256>>>(fc1, Wf2, bf2, out);
}

// round 14
// speedup vs baseline: 1.5114x; 1.5114x over previous
#include <cuda_runtime.h>
#include <cuda_bf16.h>
#include <cstdint>

// ---------------- static scratch (no runtime allocation allowed) ----------------
#define MAXN 100000
#define MAXE 1200000

__device__ __nv_bfloat16  g_actb[(size_t)MAXN * 128];   // layer outputs h1(64)/h2(128), bf16
__device__ __nv_bfloat16  g_bufY[(size_t)MAXN * 128];   // aggregated features (bf16)
__device__ __nv_bfloat16  g_featb[(size_t)MAXN * 64];   // bf16 copy of input features
__device__ float2 g_dc[MAXN];                  // (weighted degree, count)
__device__ float  g_dinv[MAXN];                // d^{-1/2}
__device__ int    g_rowptr[MAXN + 1];
__device__ int    g_woff[MAXN + 1];
__device__ int    g_bsums[128];
__device__ int2   g_csr[MAXE];                 // packed (src, norm)
__device__ int    g_segstart[257];
__device__ __nv_bfloat16 g_whiT[45056];        // bf16-hi of W1|W2|W3, TRANSPOSED [OUT][K]
__device__ __nv_bfloat16 g_wloT[45056];        // bf16 residual, transposed
__device__ float g_poolc[256 * 256];           // conv3 segment sums (fp32, atomically built)
__device__ float g_poolf[256 * 64];            // feature segment sums
__device__ float g_fc1[256 * 1024];

// ---------------- helpers ----------------
__device__ __forceinline__ void bf8_to_f8(uint4 v, float* f) {
    const __nv_bfloat162* p = reinterpret_cast<const __nv_bfloat162*>(&v);
    #pragma unroll
    for (int j = 0; j < 4; j++) {
        float2 t = __bfloat1622float2(p[j]);
        f[2 * j] = t.x; f[2 * j + 1] = t.y;
    }
}

__device__ __forceinline__ void cp_async16(void* smem, const void* gmem, int src_bytes) {
    uint32_t s = (uint32_t)__cvta_generic_to_shared(smem);
    asm volatile("cp.async.cg.shared.global [%0], [%1], 16, %2;" :: "r"(s), "l"(gmem), "r"(src_bytes));
}
#define CP_COMMIT asm volatile("cp.async.commit_group;")

// ---------------- fused prep: wsplit | featcvt | seg_bounds | deg_init | zero poolc ----------------
__global__ void prep_kernel(const float* __restrict__ W1, const float* __restrict__ W2,
                            const float* __restrict__ W3, __nv_bfloat16* __restrict__ hi,
                            __nv_bfloat16* __restrict__ lo,
                            const float* __restrict__ feature, __nv_bfloat16* __restrict__ featb,
                            const int* __restrict__ pb, int* __restrict__ segstart,
                            float2* __restrict__ dc, float* __restrict__ poolc,
                            int N, int nWS, int nFC, int nDI) {
    int b = blockIdx.x, t = threadIdx.x;
    if (b < nWS) {
        int i = b * 256 + t;
        if (i < 45056) {
            float w; int o;
            if (i < 4096)       { int k = i >> 6, n = i & 63;  w = W1[i];          o = n * 64 + k; }
            else if (i < 12288) { int j = i - 4096;  int k = j >> 7, n = j & 127; w = W2[j]; o = 4096  + n * 64  + k; }
            else                { int j = i - 12288; int k = j >> 8, n = j & 255; w = W3[j]; o = 12288 + n * 128 + k; }
            __nv_bfloat16 h = __float2bfloat16(w);
            hi[o] = h;
            lo[o] = __float2bfloat16(w - __bfloat162float(h));
        }
    } else if (b < nWS + nFC) {
        int i = (b - nWS) * 256 + t;
        if (i < N * 16) {
            float4 v = reinterpret_cast<const float4*>(feature)[i];
            __nv_bfloat162* o = reinterpret_cast<__nv_bfloat162*>(featb) + i * 2;
            o[0] = __floats2bfloat162_rn(v.x, v.y);
            o[1] = __floats2bfloat162_rn(v.z, v.w);
        }
    } else if (b < nWS + nFC + 2) {
        int s = (b - nWS - nFC) * 256 + t;
        if (s <= 256) {
            int lo2 = 0, hi2 = N;
            while (lo2 < hi2) {
                int mid = (lo2 + hi2) >> 1;
                if (pb[mid] < s) lo2 = mid + 1; else hi2 = mid;
            }
            segstart[s] = lo2;
        }
    } else if (b < nWS + nFC + 2 + nDI) {
        int i = (b - nWS - nFC - 2) * 256 + t;
        if (i < N) dc[i] = make_float2(1.0f, 0.0f);   // self-loop weight
    } else {
        int i = (b - nWS - nFC - 2 - nDI) * 256 + t;
        if (i < 256 * 256) poolc[i] = 0.0f;
    }
}

__global__ void deg_acc_kernel(const int* __restrict__ dst, const float* __restrict__ w,
                               float2* __restrict__ dc, int E) {
    int e = blockIdx.x * blockDim.x + threadIdx.x;
    if (e < E) atomicAdd(&dc[dst[e]], make_float2(w[e], 1.0f));
}

// ---------------- scan: cnt -> rowptr (exclusive); dinv folded in ----------------
__global__ void scan_block_kernel(const float2* __restrict__ dc, int* __restrict__ rowptr,
                                  int* __restrict__ bsums, float* __restrict__ dinv, int N) {
    __shared__ int sh[1024];
    int i = blockIdx.x * 1024 + threadIdx.x;
    int v = 0;
    if (i < N) {
        float2 d = dc[i];
        v = (int)(d.y + 0.5f);
        dinv[i] = rsqrtf(d.x);            // deg >= 1 (self-loop)
    }
    sh[threadIdx.x] = v;
    __syncthreads();
    for (int off = 1; off < 1024; off <<= 1) {
        int t = (threadIdx.x >= off) ? sh[threadIdx.x - off] : 0;
        __syncthreads();
        sh[threadIdx.x] += t;
        __syncthreads();
    }
    if (i < N) rowptr[i] = sh[threadIdx.x] - v;
    if (threadIdx.x == 1023) bsums[blockIdx.x] = sh[1023];
}

__global__ void scan_sums_kernel(int* bsums, int nb) {
    __shared__ int sh[128];
    int v = (threadIdx.x < nb) ? bsums[threadIdx.x] : 0;
    sh[threadIdx.x] = v;
    __syncthreads();
    for (int off = 1; off < 128; off <<= 1) {
        int t = (threadIdx.x >= off) ? sh[threadIdx.x - off] : 0;
        __syncthreads();
        sh[threadIdx.x] += t;
        __syncthreads();
    }
    if (threadIdx.x < nb) bsums[threadIdx.x] = sh[threadIdx.x] - v;
}

__global__ void add_off_kernel(int* __restrict__ rowptr, const int* __restrict__ bsums,
                               int* __restrict__ woff, int N, int E) {
    int i = blockIdx.x * blockDim.x + threadIdx.x;
    if (i < N) {
        int r = rowptr[i] + bsums[i >> 10];
        rowptr[i] = r;
        woff[i] = r;
    }
    if (i == N) rowptr[N] = E;
}

__global__ void place_kernel(const int* __restrict__ src, const int* __restrict__ dst,
                             const float* __restrict__ w, const float* __restrict__ dinv,
                             int* __restrict__ woff, int2* __restrict__ csr, int E) {
    int e = blockIdx.x * blockDim.x + threadIdx.x;
    if (e >= E) return;
    int s = src[e], d = dst[e];
    float nr = dinv[s] * w[e] * dinv[d];
    int pos = atomicAdd(&woff[d], 1);
    csr[pos] = make_int2(s, __float_as_int(nr));
}

// ---------------- CSR gather aggregation (bf16 in/out, fp32 accumulate) ----------------
template<int IN>
__global__ void gather_kernel(const int* __restrict__ rowptr, const int2* __restrict__ csr,
                              const __nv_bfloat16* __restrict__ X, const float* __restrict__ dinv,
                              __nv_bfloat16* __restrict__ Y, int N) {
    const int G = IN / 8;                 // threads per node (8 bf16 = 16B each)
    const int NPB = 256 / G;
    int lane = threadIdx.x % G;
    int node = blockIdx.x * NPB + threadIdx.x / G;
    if (node >= N) return;

    int beg = rowptr[node];
    int end = rowptr[node + 1];
    float di = dinv[node];
    float sl = di * di;

    float acc[8];
    {
        uint4 xv = *reinterpret_cast<const uint4*>(&X[(size_t)node * IN + lane * 8]);
        float xf[8]; bf8_to_f8(xv, xf);
        #pragma unroll
        for (int j = 0; j < 8; j++) acc[j] = sl * xf[j];
    }

    int k = beg;
    for (; k + 4 <= end; k += 4) {
        int2 p0 = csr[k], p1 = csr[k + 1], p2 = csr[k + 2], p3 = csr[k + 3];
        uint4 v0 = *reinterpret_cast<const uint4*>(&X[(size_t)p0.x * IN + lane * 8]);
        uint4 v1 = *reinterpret_cast<const uint4*>(&X[(size_t)p1.x * IN + lane * 8]);
        uint4 v2 = *reinterpret_cast<const uint4*>(&X[(size_t)p2.x * IN + lane * 8]);
        uint4 v3 = *reinterpret_cast<const uint4*>(&X[(size_t)p3.x * IN + lane * 8]);
        float n0 = __int_as_float(p0.y), n1 = __int_as_float(p1.y);
        float n2 = __int_as_float(p2.y), n3 = __int_as_float(p3.y);
        float f0[8], f1[8], f2[8], f3[8];
        bf8_to_f8(v0, f0); bf8_to_f8(v1, f1); bf8_to_f8(v2, f2); bf8_to_f8(v3, f3);
        #pragma unroll
        for (int j = 0; j < 8; j++)
            acc[j] += n0 * f0[j] + n1 * f1[j] + n2 * f2[j] + n3 * f3[j];
    }
    for (; k < end; k++) {
        int2 p0 = csr[k];
        float n0 = __int_as_float(p0.y);
        uint4 v0 = *reinterpret_cast<const uint4*>(&X[(size_t)p0.x * IN + lane * 8]);
        float f0[8]; bf8_to_f8(v0, f0);
        #pragma unroll
        for (int j = 0; j < 8; j++) acc[j] += n0 * f0[j];
    }

    uint4 o;
    __nv_bfloat162* q = reinterpret_cast<__nv_bfloat162*>(&o);
    #pragma unroll
    for (int j = 0; j < 4; j++) q[j] = __floats2bfloat162_rn(acc[2 * j], acc[2 * j + 1]);
    *reinterpret_cast<uint4*>(&Y[(size_t)node * IN + lane * 8]) = o;
}

// ---------------- bf16 tensor-core GEMM, cp.async double-buffered ----------------
// H = relu(A @ (Whi + Wlo) + bias). POOL=false: bf16 store.
// POOL=true: h3 never stored — fp32 tile staged in (reused) smem, then a
// conflict-free segmented reduction over sorted rows flushes per-segment
// run-sums with a handful of distinct-address global atomics. NO smem atomics.
template<int OUT, int K, bool POOL>
__global__ void __launch_bounds__(256) bf16_gemm_kernel(
    const __nv_bfloat16* __restrict__ A, const __nv_bfloat16* __restrict__ BhiT,
    const __nv_bfloat16* __restrict__ BloT, const float* __restrict__ bias,
    __nv_bfloat16* __restrict__ Cout, const int* __restrict__ pb,
    float* __restrict__ poolc, int N)
{
    constexpr int NITER = K / 32;
    // 40960 bytes shared by the MMA staging buffers and (later) the POOL tile
    __shared__ __align__(16) char smem_raw[40960];
    typedef __nv_bfloat16 (*AsP)[128][40];
    typedef __nv_bfloat16 (*BP)[64][40];
    AsP As = reinterpret_cast<AsP>(smem_raw);               // As[2][128][40]
    BP  Bh = reinterpret_cast<BP>(smem_raw + 20480);        // Bh[2][64][40]
    BP  Bl = reinterpret_cast<BP>(smem_raw + 30720);        // Bl[2][64][40]

    int t = threadIdx.x;
    int lane = t & 31, w = t >> 5;
    int warpM = w & 3, warpN = w >> 2;
    int g = lane >> 2, tc = lane & 3;
    int rowBase = blockIdx.x * 128;
    int colBase = blockIdx.y * 64;

    int am0 = t >> 2, akq = (t & 3) * 8;
    int am1 = am0 + 64;
    int bn = t >> 2, bkq = (t & 3) * 8;

    auto load_tile = [&](int kb, int buf) {
        const __nv_bfloat16* a0 = &A[(size_t)(rowBase + am0) * K + kb + akq];
        const __nv_bfloat16* a1 = &A[(size_t)(rowBase + am1) * K + kb + akq];
        cp_async16(&As[buf][am0][akq], (rowBase + am0 < N) ? a0 : A, (rowBase + am0 < N) ? 16 : 0);
        cp_async16(&As[buf][am1][akq], (rowBase + am1 < N) ? a1 : A, (rowBase + am1 < N) ? 16 : 0);
        cp_async16(&Bh[buf][bn][bkq], &BhiT[(size_t)(colBase + bn) * K + kb + bkq], 16);
        cp_async16(&Bl[buf][bn][bkq], &BloT[(size_t)(colBase + bn) * K + kb + bkq], 16);
    };

    float acc[2][4][4];
    #pragma unroll
    for (int a = 0; a < 2; a++)
        #pragma unroll
        for (int b = 0; b < 4; b++)
            #pragma unroll
            for (int c = 0; c < 4; c++) acc[a][b][c] = 0.0f;

    load_tile(0, 0);
    CP_COMMIT;

    #pragma unroll
    for (int it = 0; it < NITER; it++) {
        if (it + 1 < NITER) {
            load_tile((it + 1) * 32, (it + 1) & 1);
            CP_COMMIT;
            asm volatile("cp.async.wait_group 1;");
        } else {
            asm volatile("cp.async.wait_group 0;");
        }
        __syncthreads();
        int buf = it & 1;

        #pragma unroll
        for (int ks = 0; ks < 32; ks += 16) {
            uint32_t af[2][4];
            #pragma unroll
            for (int mt = 0; mt < 2; mt++) {
                int m0 = warpM * 32 + mt * 16 + g;
                af[mt][0] = *reinterpret_cast<const uint32_t*>(&As[buf][m0][ks + tc * 2]);
                af[mt][1] = *reinterpret_cast<const uint32_t*>(&As[buf][m0 + 8][ks + tc * 2]);
                af[mt][2] = *reinterpret_cast<const uint32_t*>(&As[buf][m0][ks + tc * 2 + 8]);
                af[mt][3] = *reinterpret_cast<const uint32_t*>(&As[buf][m0 + 8][ks + tc * 2 + 8]);
            }
            #pragma unroll
            for (int nt = 0; nt < 4; nt++) {
                int n0 = warpN * 32 + nt * 8 + g;
                uint32_t bh0 = *reinterpret_cast<const uint32_t*>(&Bh[buf][n0][ks + tc * 2]);
                uint32_t bh1 = *reinterpret_cast<const uint32_t*>(&Bh[buf][n0][ks + tc * 2 + 8]);
                uint32_t bl0 = *reinterpret_cast<const uint32_t*>(&Bl[buf][n0][ks + tc * 2]);
                uint32_t bl1 = *reinterpret_cast<const uint32_t*>(&Bl[buf][n0][ks + tc * 2 + 8]);
                #pragma unroll
                for (int mt = 0; mt < 2; mt++) {
                    float* c = acc[mt][nt];
                    asm volatile(
                        "mma.sync.aligned.m16n8k16.row.col.f32.bf16.bf16.f32 "
                        "{%0,%1,%2,%3}, {%4,%5,%6,%7}, {%8,%9}, {%0,%1,%2,%3};"
                        : "+f"(c[0]), "+f"(c[1]), "+f"(c[2]), "+f"(c[3])
                        : "r"(af[mt][0]), "r"(af[mt][1]), "r"(af[mt][2]), "r"(af[mt][3]),
                          "r"(bh0), "r"(bh1));
                    asm volatile(
                        "mma.sync.aligned.m16n8k16.row.col.f32.bf16.bf16.f32 "
                        "{%0,%1,%2,%3}, {%4,%5,%6,%7}, {%8,%9}, {%0,%1,%2,%3};"
                        : "+f"(c[0]), "+f"(c[1]), "+f"(c[2]), "+f"(c[3])
                        : "r"(af[mt][0]), "r"(af[mt][1]), "r"(af[mt][2]), "r"(af[mt][3]),
                          "r"(bl0), "r"(bl1));
                }
            }
        }
        __syncthreads();
    }

    if (!POOL) {
        // epilogue: bias + relu, bf16 out
        #pragma unroll
        for (int mt = 0; mt < 2; mt++) {
            #pragma unroll
            for (int nt = 0; nt < 4; nt++) {
                int row = rowBase + warpM * 32 + mt * 16 + g;
                int col = colBase + warpN * 32 + nt * 8 + tc * 2;
                float b0 = bias[col], b1 = bias[col + 1];
                float* c = acc[mt][nt];
                if (row < N)
                    *reinterpret_cast<__nv_bfloat162*>(&Cout[(size_t)row * OUT + col]) =
                        __floats2bfloat162_rn(fmaxf(c[0] + b0, 0.f), fmaxf(c[1] + b1, 0.f));
                if (row + 8 < N)
                    *reinterpret_cast<__nv_bfloat162*>(&Cout[(size_t)(row + 8) * OUT + col]) =
                        __floats2bfloat162_rn(fmaxf(c[2] + b0, 0.f), fmaxf(c[3] + b1, 0.f));
            }
        }
    } else {
        // epilogue v2: stage fp32 tile in reused smem (plain stores), then
        // conflict-free segmented reduction over the sorted 128-row chunk.
        float* tile = reinterpret_cast<float*>(smem_raw);     // [128][65], 33280 B
        int* pbs = reinterpret_cast<int*>(smem_raw + 33280);  // [128]
        // (last loop iteration ended with __syncthreads(); smem is free)
        #pragma unroll
        for (int mt = 0; mt < 2; mt++) {
            #pragma unroll
            for (int nt = 0; nt < 4; nt++) {
                int row = warpM * 32 + mt * 16 + g;
                int cl = warpN * 32 + nt * 8 + tc * 2;
                float b0 = bias[colBase + cl], b1 = bias[colBase + cl + 1];
                float* c = acc[mt][nt];
                tile[row * 65 + cl]           = fmaxf(c[0] + b0, 0.f);
                tile[row * 65 + cl + 1]       = fmaxf(c[1] + b1, 0.f);
                tile[(row + 8) * 65 + cl]     = fmaxf(c[2] + b0, 0.f);
                tile[(row + 8) * 65 + cl + 1] = fmaxf(c[3] + b1, 0.f);
            }
        }
        if (t < 128) pbs[t] = (rowBase + t < N) ? pb[rowBase + t] : -1;
        __syncthreads();

        int cl = t & 63;
        int r0 = (t >> 6) * 32;
        float run = 0.0f;
        int cur = pbs[r0];
        #pragma unroll 4
        for (int r = r0; r < r0 + 32; r++) {
            int sg = pbs[r];
            if (sg != cur) {
                if (cur >= 0 && run != 0.0f)
                    atomicAdd(&poolc[cur * 256 + colBase + cl], run);
                run = 0.0f;
                cur = sg;
            }
            if (sg >= 0) run += tile[r * 65 + cl];
        }
        if (cur >= 0 && run != 0.0f)
            atomicAdd(&poolc[cur * 256 + colBase + cl], run);
    }
}

// ---------------- feature pooling: per-segment fp32 sums ----------------
__global__ void featpool_kernel(const float* __restrict__ feature,
                                const int* __restrict__ segstart, float* __restrict__ poolf) {
    __shared__ float4 sh[16][16];
    int seg = blockIdx.x;
    int c = threadIdx.x % 16;
    int r = threadIdx.x / 16;
    int beg = segstart[seg], end = segstart[seg + 1];

    float4 acc = make_float4(0.f, 0.f, 0.f, 0.f);
    for (int i = beg + r; i < end; i += 16) {
        float4 v = *reinterpret_cast<const float4*>(&feature[(size_t)i * 64 + c * 4]);
        acc.x += v.x; acc.y += v.y; acc.z += v.z; acc.w += v.w;
    }
    sh[r][c] = acc;
    __syncthreads();
    for (int s = 8; s > 0; s >>= 1) {
        if (r < s) {
            float4 a = sh[r][c], b = sh[r + s][c];
            sh[r][c] = make_float4(a.x + b.x, a.y + b.y, a.z + b.z, a.w + b.w);
        }
        __syncthreads();
    }
    if (r == 0)
        *reinterpret_cast<float4*>(&poolf[seg * 64 + c * 4]) = sh[0][c];
}

// ---------------- MLP head ----------------
__global__ void fc1_kernel(const float* __restrict__ poolc, const float* __restrict__ poolf,
                           const int* __restrict__ segstart,
                           const float* __restrict__ Wf1, const float* __restrict__ bf1,
                           float* __restrict__ fc1) {
    __shared__ float srow[8][320];
    __shared__ float sinv[8];
    int rowBase = blockIdx.y * 8;
    int col = blockIdx.x * 256 + threadIdx.x;

    for (int lin = threadIdx.x; lin < 8 * 320; lin += 256) {
        int rr = lin / 320, k = lin % 320;
        int row = rowBase + rr;
        srow[rr][k] = (k < 256) ? poolc[row * 256 + k] : poolf[row * 64 + (k - 256)];
    }
    if (threadIdx.x < 8) {
        int row = rowBase + threadIdx.x;
        int c = segstart[row + 1] - segstart[row];
        sinv[threadIdx.x] = 1.0f / fmaxf((float)c, 1.0f);
    }
    __syncthreads();

    float acc[8] = {};
    #pragma unroll 4
    for (int k = 0; k < 320; k++) {
        float wv = Wf1[(size_t)k * 1024 + col];
        #pragma unroll
        for (int rr = 0; rr < 8; rr++) acc[rr] += srow[rr][k] * wv;
    }
    float b = bf1[col];
    #pragma unroll
    for (int rr = 0; rr < 8; rr++) {
        float v = acc[rr] * sinv[rr] + b;
        fc1[(size_t)(rowBase + rr) * 1024 + col] = fmaxf(v, 0.f);
    }
}

__global__ void fc2_kernel(const float* __restrict__ fc1, const float* __restrict__ Wf2,
                           const float* __restrict__ bf2, float* __restrict__ out) {
    int row = blockIdx.x;
    float a = 0.f;
    for (int j = threadIdx.x; j < 1024; j += 256)
        a += fc1[(size_t)row * 1024 + j] * Wf2[j];
    __shared__ float red[256];
    red[threadIdx.x] = a;
    __syncthreads();
    for (int s = 128; s > 0; s >>= 1) {
        if (threadIdx.x < s) red[threadIdx.x] += red[threadIdx.x + s];
        __syncthreads();
    }
    if (threadIdx.x == 0) out[row] = red[0] + bf2[0];
}

// ---------------- launch ----------------
extern "C" void kernel_launch(void* const* d_in, const int* in_sizes, int n_in,
                              void* d_out, int out_size) {
    const float* feature = (const float*)d_in[0];
    const int*   ei      = (const int*)d_in[1];
    const float* weight  = (const float*)d_in[2];
    const int*   pb      = (const int*)d_in[3];
    const float* W1 = (const float*)d_in[4];  const float* b1  = (const float*)d_in[5];
    const float* W2 = (const float*)d_in[6];  const float* b2  = (const float*)d_in[7];
    const float* W3 = (const float*)d_in[8];  const float* b3  = (const float*)d_in[9];
    const float* Wf1 = (const float*)d_in[10]; const float* bf1 = (const float*)d_in[11];
    const float* Wf2 = (const float*)d_in[12]; const float* bf2 = (const float*)d_in[13];
    float* out = (float*)d_out;

    int N = in_sizes[0] / 64;
    int E = in_sizes[2];
    const int* src = ei;
    const int* dst = ei + E;

    float *dinv, *poolc, *poolf, *fc1;
    __nv_bfloat16 *actb, *bufY, *featb, *whiT, *wloT;
    float2 *dc;
    int *rowptr, *woff, *bsums, *segstart;
    int2 *csr;
    cudaGetSymbolAddress((void**)&actb, g_actb);
    cudaGetSymbolAddress((void**)&bufY, g_bufY);
    cudaGetSymbolAddress((void**)&featb, g_featb);
    cudaGetSymbolAddress((void**)&dc, g_dc);
    cudaGetSymbolAddress((void**)&dinv, g_dinv);
    cudaGetSymbolAddress((void**)&rowptr, g_rowptr);
    cudaGetSymbolAddress((void**)&woff, g_woff);
    cudaGetSymbolAddress((void**)&bsums, g_bsums);
    cudaGetSymbolAddress((void**)&csr, g_csr);
    cudaGetSymbolAddress((void**)&segstart, g_segstart);
    cudaGetSymbolAddress((void**)&whiT, g_whiT);
    cudaGetSymbolAddress((void**)&wloT, g_wloT);
    cudaGetSymbolAddress((void**)&poolc, g_poolc);
    cudaGetSymbolAddress((void**)&poolf, g_poolf);
    cudaGetSymbolAddress((void**)&fc1,  g_fc1);

    const int T = 256;
    int nb = (N + 1023) / 1024;
    int nWS = (45056 + 255) / 256;
    int nFC = (N * 16 + 255) / 256;
    int nDI = (N + 255) / 256;
    int nPZ = 256;   // zero 256*256 poolc

    // fused prep
    prep_kernel<<<nWS + nFC + 2 + nDI + nPZ, T>>>(W1, W2, W3, whiT, wloT, feature, featb,
                                                  pb, segstart, dc, poolc, N, nWS, nFC, nDI);
    deg_acc_kernel<<<(E + T - 1) / T, T>>>(dst, weight, dc, E);
    scan_block_kernel<<<nb, 1024>>>(dc, rowptr, bsums, dinv, N);
    scan_sums_kernel<<<1, 128>>>(bsums, nb);
    add_off_kernel<<<(N + 1 + T - 1) / T, T>>>(rowptr, bsums, woff, N, E);
    place_kernel<<<(E + T - 1) / T, T>>>(src, dst, weight, dinv, woff, csr, E);

    int gb128 = (N + 127) / 128;

    // layer 1: [N,64] -> [N,64]
    gather_kernel<64><<<(N * 8 + 255) / 256, 256>>>(rowptr, csr, featb, dinv, bufY, N);
    bf16_gemm_kernel<64, 64, false><<<dim3(gb128, 1), 256>>>(bufY, whiT, wloT, b1, actb, nullptr, nullptr, N);

    // layer 2: [N,64] -> [N,128]
    gather_kernel<64><<<(N * 8 + 255) / 256, 256>>>(rowptr, csr, actb, dinv, bufY, N);
    bf16_gemm_kernel<128, 64, false><<<dim3(gb128, 2), 256>>>(bufY, whiT + 4096, wloT + 4096, b2, actb, nullptr, nullptr, N);

    // layer 3: [N,128] -> pooled segment sums directly (h3 never stored)
    gather_kernel<128><<<(N * 16 + 255) / 256, 256>>>(rowptr, csr, actb, dinv, bufY, N);
    bf16_gemm_kernel<256, 128, true><<<dim3(gb128, 4), 256>>>(bufY, whiT + 12288, wloT + 12288, b3, nullptr, pb, poolc, N);

    // feature pooling (fp32 source) + MLP head
    featpool_kernel<<<256, 256>>>(feature, segstart, poolf);
    fc1_kernel<<<dim3(4, 32), 256>>>(poolc, poolf, segstart, Wf1, bf1, fc1);
    fc2_kernel<<<256, 256>>>(fc1, Wf2, bf2, out);
}

// round 15
// speedup vs baseline: 1.5297x; 1.0121x over previous
#include <cuda_runtime.h>
#include <cuda_bf16.h>
#include <cstdint>

// ---------------- static scratch (no runtime allocation allowed) ----------------
#define MAXN 100000
#define MAXE 1200000

__device__ __nv_bfloat16  g_actb[(size_t)MAXN * 128];   // layer outputs h1(64)/h2(128), bf16
__device__ __nv_bfloat16  g_bufY[(size_t)MAXN * 128];   // aggregated features (bf16)
__device__ __nv_bfloat16  g_featb[(size_t)MAXN * 64];   // bf16 copy of input features
__device__ float2 g_dc[MAXN];                  // (weighted degree, count)
__device__ float  g_dinv[MAXN];                // d^{-1/2}
__device__ int    g_rowptr[MAXN + 1];
__device__ int    g_woff[MAXN + 1];
__device__ int    g_bsums[128];
__device__ int2   g_csr[MAXE];                 // packed (src, norm)
__device__ int    g_segstart[257];
__device__ __nv_bfloat16 g_whiT[45056];        // bf16-hi of W1|W2|W3, TRANSPOSED [OUT][K]
__device__ __nv_bfloat16 g_wloT[45056];        // bf16 residual, transposed
__device__ float g_poolc[256 * 256];           // conv3 segment sums (fp32)
__device__ float g_poolf[256 * 64];            // feature segment sums
__device__ float g_fc1[256 * 1024];

// ---------------- helpers ----------------
__device__ __forceinline__ void bf8_to_f8(uint4 v, float* f) {
    const __nv_bfloat162* p = reinterpret_cast<const __nv_bfloat162*>(&v);
    #pragma unroll
    for (int j = 0; j < 4; j++) {
        float2 t = __bfloat1622float2(p[j]);
        f[2 * j] = t.x; f[2 * j + 1] = t.y;
    }
}

__device__ __forceinline__ void cp_async16(void* smem, const void* gmem, int src_bytes) {
    uint32_t s = (uint32_t)__cvta_generic_to_shared(smem);
    asm volatile("cp.async.cg.shared.global [%0], [%1], 16, %2;" :: "r"(s), "l"(gmem), "r"(src_bytes));
}
#define CP_COMMIT asm volatile("cp.async.commit_group;")

// ---------------- fused prep: wsplit | featcvt | seg_bounds | deg_init | zero poolc ----------------
__global__ void prep_kernel(const float* __restrict__ W1, const float* __restrict__ W2,
                            const float* __restrict__ W3, __nv_bfloat16* __restrict__ hi,
                            __nv_bfloat16* __restrict__ lo,
                            const float* __restrict__ feature, __nv_bfloat16* __restrict__ featb,
                            const int* __restrict__ pb, int* __restrict__ segstart,
                            float2* __restrict__ dc, float* __restrict__ poolc,
                            int N, int nWS, int nFC, int nDI) {
    int b = blockIdx.x, t = threadIdx.x;
    if (b < nWS) {
        int i = b * 256 + t;
        if (i < 45056) {
            float w; int o;
            if (i < 4096)       { int k = i >> 6, n = i & 63;  w = W1[i];          o = n * 64 + k; }
            else if (i < 12288) { int j = i - 4096;  int k = j >> 7, n = j & 127; w = W2[j]; o = 4096  + n * 64  + k; }
            else                { int j = i - 12288; int k = j >> 8, n = j & 255; w = W3[j]; o = 12288 + n * 128 + k; }
            __nv_bfloat16 h = __float2bfloat16(w);
            hi[o] = h;
            lo[o] = __float2bfloat16(w - __bfloat162float(h));
        }
    } else if (b < nWS + nFC) {
        int i = (b - nWS) * 256 + t;
        if (i < N * 16) {
            float4 v = reinterpret_cast<const float4*>(feature)[i];
            __nv_bfloat162* o = reinterpret_cast<__nv_bfloat162*>(featb) + i * 2;
            o[0] = __floats2bfloat162_rn(v.x, v.y);
            o[1] = __floats2bfloat162_rn(v.z, v.w);
        }
    } else if (b < nWS + nFC + 2) {
        int s = (b - nWS - nFC) * 256 + t;
        if (s <= 256) {
            int lo2 = 0, hi2 = N;
            while (lo2 < hi2) {
                int mid = (lo2 + hi2) >> 1;
                if (pb[mid] < s) lo2 = mid + 1; else hi2 = mid;
            }
            segstart[s] = lo2;
        }
    } else if (b < nWS + nFC + 2 + nDI) {
        int i = (b - nWS - nFC - 2) * 256 + t;
        if (i < N) dc[i] = make_float2(1.0f, 0.0f);   // self-loop weight
    } else {
        int i = (b - nWS - nFC - 2 - nDI) * 256 + t;
        if (i < 256 * 256) poolc[i] = 0.0f;
    }
}

__global__ void deg_acc_kernel(const int* __restrict__ dst, const float* __restrict__ w,
                               float2* __restrict__ dc, int E) {
    int e = blockIdx.x * blockDim.x + threadIdx.x;
    if (e < E) atomicAdd(&dc[dst[e]], make_float2(w[e], 1.0f));
}

// ---------------- scan: cnt -> block-local rowptr + block sums; dinv folded in ----------------
__global__ void scan_block_kernel(const float2* __restrict__ dc, int* __restrict__ rowptr,
                                  int* __restrict__ bsums, float* __restrict__ dinv, int N) {
    __shared__ int sh[1024];
    int i = blockIdx.x * 1024 + threadIdx.x;
    int v = 0;
    if (i < N) {
        float2 d = dc[i];
        v = (int)(d.y + 0.5f);
        dinv[i] = rsqrtf(d.x);            // deg >= 1 (self-loop)
    }
    sh[threadIdx.x] = v;
    __syncthreads();
    for (int off = 1; off < 1024; off <<= 1) {
        int t = (threadIdx.x >= off) ? sh[threadIdx.x - off] : 0;
        __syncthreads();
        sh[threadIdx.x] += t;
        __syncthreads();
    }
    if (i < N) rowptr[i] = sh[threadIdx.x] - v;
    if (threadIdx.x == 1023) bsums[blockIdx.x] = sh[1023];
}

// add_off with fused block-sum scan: each block re-scans bsums (<=128 entries) in smem
__global__ void add_off_kernel(int* __restrict__ rowptr, const int* __restrict__ bsums,
                               int* __restrict__ woff, int N, int E, int nb) {
    __shared__ int pref[128];
    int t = threadIdx.x;
    if (t < 128) pref[t] = (t < nb) ? bsums[t] : 0;
    __syncthreads();
    for (int off = 1; off < 128; off <<= 1) {
        int x = (t < 128 && t >= off) ? pref[t - off] : 0;
        __syncthreads();
        if (t < 128) pref[t] += x;     // inclusive scan
        __syncthreads();
    }
    int i = blockIdx.x * 256 + t;
    if (i < N) {
        int blk = i >> 10;
        int ex = (blk == 0) ? 0 : pref[blk - 1];
        int r = rowptr[i] + ex;
        rowptr[i] = r;
        woff[i] = r;
    }
    if (i == N) rowptr[N] = E;
}

__global__ void place_kernel(const int* __restrict__ src, const int* __restrict__ dst,
                             const float* __restrict__ w, const float* __restrict__ dinv,
                             int* __restrict__ woff, int2* __restrict__ csr, int E) {
    int e = blockIdx.x * blockDim.x + threadIdx.x;
    if (e >= E) return;
    int s = src[e], d = dst[e];
    float nr = dinv[s] * w[e] * dinv[d];
    int pos = atomicAdd(&woff[d], 1);
    csr[pos] = make_int2(s, __float_as_int(nr));
}

// ---------------- CSR gather aggregation (bf16 in/out, fp32 accumulate) ----------------
template<int IN>
__global__ void gather_kernel(const int* __restrict__ rowptr, const int2* __restrict__ csr,
                              const __nv_bfloat16* __restrict__ X, const float* __restrict__ dinv,
                              __nv_bfloat16* __restrict__ Y, int N) {
    const int G = IN / 8;                 // threads per node (8 bf16 = 16B each)
    const int NPB = 256 / G;
    int lane = threadIdx.x % G;
    int node = blockIdx.x * NPB + threadIdx.x / G;
    if (node >= N) return;

    int beg = rowptr[node];
    int end = rowptr[node + 1];
    float di = dinv[node];
    float sl = di * di;

    float acc[8];
    {
        uint4 xv = *reinterpret_cast<const uint4*>(&X[(size_t)node * IN + lane * 8]);
        float xf[8]; bf8_to_f8(xv, xf);
        #pragma unroll
        for (int j = 0; j < 8; j++) acc[j] = sl * xf[j];
    }

    int k = beg;
    for (; k + 4 <= end; k += 4) {
        int2 p0 = csr[k], p1 = csr[k + 1], p2 = csr[k + 2], p3 = csr[k + 3];
        uint4 v0 = *reinterpret_cast<const uint4*>(&X[(size_t)p0.x * IN + lane * 8]);
        uint4 v1 = *reinterpret_cast<const uint4*>(&X[(size_t)p1.x * IN + lane * 8]);
        uint4 v2 = *reinterpret_cast<const uint4*>(&X[(size_t)p2.x * IN + lane * 8]);
        uint4 v3 = *reinterpret_cast<const uint4*>(&X[(size_t)p3.x * IN + lane * 8]);
        float n0 = __int_as_float(p0.y), n1 = __int_as_float(p1.y);
        float n2 = __int_as_float(p2.y), n3 = __int_as_float(p3.y);
        float f0[8], f1[8], f2[8], f3[8];
        bf8_to_f8(v0, f0); bf8_to_f8(v1, f1); bf8_to_f8(v2, f2); bf8_to_f8(v3, f3);
        #pragma unroll
        for (int j = 0; j < 8; j++)
            acc[j] += n0 * f0[j] + n1 * f1[j] + n2 * f2[j] + n3 * f3[j];
    }
    for (; k < end; k++) {
        int2 p0 = csr[k];
        float n0 = __int_as_float(p0.y);
        uint4 v0 = *reinterpret_cast<const uint4*>(&X[(size_t)p0.x * IN + lane * 8]);
        float f0[8]; bf8_to_f8(v0, f0);
        #pragma unroll
        for (int j = 0; j < 8; j++) acc[j] += n0 * f0[j];
    }

    uint4 o;
    __nv_bfloat162* q = reinterpret_cast<__nv_bfloat162*>(&o);
    #pragma unroll
    for (int j = 0; j < 4; j++) q[j] = __floats2bfloat162_rn(acc[2 * j], acc[2 * j + 1]);
    *reinterpret_cast<uint4*>(&Y[(size_t)node * IN + lane * 8]) = o;
}

// ---------------- bf16 tensor-core GEMM, cp.async double-buffered, wide-BN ----------------
// H = relu(A @ (Whi + Wlo) + bias). BM=128, BN in {64,128}, BK=32, 8 warps (4M x 2N).
// POOL=true: h3 never stored — fp32 tile staged in reused smem, conflict-free
// segmented reduction over sorted rows, distinct-address global atomics only.
template<int OUT, int K, int BN, bool POOL>
__global__ void __launch_bounds__(256) bf16_gemm_kernel(
    const __nv_bfloat16* __restrict__ A, const __nv_bfloat16* __restrict__ BhiT,
    const __nv_bfloat16* __restrict__ BloT, const float* __restrict__ bias,
    __nv_bfloat16* __restrict__ Cout, const int* __restrict__ pb,
    float* __restrict__ poolc, int N)
{
    constexpr int NITER = K / 32;
    constexpr int WN = BN / 2;        // per-warp N extent
    constexpr int NT = WN / 8;        // n-tiles per warp
    extern __shared__ __align__(16) char smem_raw[];
    auto As = reinterpret_cast<__nv_bfloat16 (*)[128][40]>(smem_raw);             // [2][128][40]
    auto Bh = reinterpret_cast<__nv_bfloat16 (*)[BN][40]>(smem_raw + 20480);      // [2][BN][40]
    auto Bl = reinterpret_cast<__nv_bfloat16 (*)[BN][40]>(smem_raw + 20480 + BN * 160);

    int t = threadIdx.x;
    int lane = t & 31, w = t >> 5;
    int warpM = w & 3, warpN = w >> 2;
    int g = lane >> 2, tc = lane & 3;
    int rowBase = blockIdx.x * 128;
    int colBase = blockIdx.y * BN;

    int am0 = t >> 2, akq = (t & 3) * 8;
    int am1 = am0 + 64;

    auto load_tile = [&](int kb, int buf) {
        const __nv_bfloat16* a0 = &A[(size_t)(rowBase + am0) * K + kb + akq];
        const __nv_bfloat16* a1 = &A[(size_t)(rowBase + am1) * K + kb + akq];
        cp_async16(&As[buf][am0][akq], (rowBase + am0 < N) ? a0 : A, (rowBase + am0 < N) ? 16 : 0);
        cp_async16(&As[buf][am1][akq], (rowBase + am1 < N) ? a1 : A, (rowBase + am1 < N) ? 16 : 0);
        #pragma unroll
        for (int i = 0; i < BN / 64; i++) {
            int lin = t + i * 256;
            int n = lin >> 2, kq = (lin & 3) * 8;
            cp_async16(&Bh[buf][n][kq], &BhiT[(size_t)(colBase + n) * K + kb + kq], 16);
            cp_async16(&Bl[buf][n][kq], &BloT[(size_t)(colBase + n) * K + kb + kq], 16);
        }
    };

    float acc[2][NT][4];
    #pragma unroll
    for (int a = 0; a < 2; a++)
        #pragma unroll
        for (int b = 0; b < NT; b++)
            #pragma unroll
            for (int c = 0; c < 4; c++) acc[a][b][c] = 0.0f;

    load_tile(0, 0);
    CP_COMMIT;

    #pragma unroll
    for (int it = 0; it < NITER; it++) {
        if (it + 1 < NITER) {
            load_tile((it + 1) * 32, (it + 1) & 1);
            CP_COMMIT;
            asm volatile("cp.async.wait_group 1;");
        } else {
            asm volatile("cp.async.wait_group 0;");
        }
        __syncthreads();
        int buf = it & 1;

        #pragma unroll
        for (int ks = 0; ks < 32; ks += 16) {
            uint32_t af[2][4];
            #pragma unroll
            for (int mt = 0; mt < 2; mt++) {
                int m0 = warpM * 32 + mt * 16 + g;
                af[mt][0] = *reinterpret_cast<const uint32_t*>(&As[buf][m0][ks + tc * 2]);
                af[mt][1] = *reinterpret_cast<const uint32_t*>(&As[buf][m0 + 8][ks + tc * 2]);
                af[mt][2] = *reinterpret_cast<const uint32_t*>(&As[buf][m0][ks + tc * 2 + 8]);
                af[mt][3] = *reinterpret_cast<const uint32_t*>(&As[buf][m0 + 8][ks + tc * 2 + 8]);
            }
            #pragma unroll
            for (int nt = 0; nt < NT; nt++) {
                int n0 = warpN * WN + nt * 8 + g;
                uint32_t bh0 = *reinterpret_cast<const uint32_t*>(&Bh[buf][n0][ks + tc * 2]);
                uint32_t bh1 = *reinterpret_cast<const uint32_t*>(&Bh[buf][n0][ks + tc * 2 + 8]);
                uint32_t bl0 = *reinterpret_cast<const uint32_t*>(&Bl[buf][n0][ks + tc * 2]);
                uint32_t bl1 = *reinterpret_cast<const uint32_t*>(&Bl[buf][n0][ks + tc * 2 + 8]);
                #pragma unroll
                for (int mt = 0; mt < 2; mt++) {
                    float* c = acc[mt][nt];
                    asm volatile(
                        "mma.sync.aligned.m16n8k16.row.col.f32.bf16.bf16.f32 "
                        "{%0,%1,%2,%3}, {%4,%5,%6,%7}, {%8,%9}, {%0,%1,%2,%3};"
                        : "+f"(c[0]), "+f"(c[1]), "+f"(c[2]), "+f"(c[3])
                        : "r"(af[mt][0]), "r"(af[mt][1]), "r"(af[mt][2]), "r"(af[mt][3]),
                          "r"(bh0), "r"(bh1));
                    asm volatile(
                        "mma.sync.aligned.m16n8k16.row.col.f32.bf16.bf16.f32 "
                        "{%0,%1,%2,%3}, {%4,%5,%6,%7}, {%8,%9}, {%0,%1,%2,%3};"
                        : "+f"(c[0]), "+f"(c[1]), "+f"(c[2]), "+f"(c[3])
                        : "r"(af[mt][0]), "r"(af[mt][1]), "r"(af[mt][2]), "r"(af[mt][3]),
                          "r"(bl0), "r"(bl1));
                }
            }
        }
        __syncthreads();
    }

    if (!POOL) {
        #pragma unroll
        for (int mt = 0; mt < 2; mt++) {
            #pragma unroll
            for (int nt = 0; nt < NT; nt++) {
                int row = rowBase + warpM * 32 + mt * 16 + g;
                int col = colBase + warpN * WN + nt * 8 + tc * 2;
                float b0 = bias[col], b1 = bias[col + 1];
                float* c = acc[mt][nt];
                if (row < N)
                    *reinterpret_cast<__nv_bfloat162*>(&Cout[(size_t)row * OUT + col]) =
                        __floats2bfloat162_rn(fmaxf(c[0] + b0, 0.f), fmaxf(c[1] + b1, 0.f));
                if (row + 8 < N)
                    *reinterpret_cast<__nv_bfloat162*>(&Cout[(size_t)(row + 8) * OUT + col]) =
                        __floats2bfloat162_rn(fmaxf(c[2] + b0, 0.f), fmaxf(c[3] + b1, 0.f));
            }
        }
    } else {
        // stage fp32 tile (plain stores), then conflict-free segmented reduction
        float* tile = reinterpret_cast<float*>(smem_raw);                 // [128][BN+1]
        int* pbs = reinterpret_cast<int*>(smem_raw + 128 * (BN + 1) * 4); // [128]
        #pragma unroll
        for (int mt = 0; mt < 2; mt++) {
            #pragma unroll
            for (int nt = 0; nt < NT; nt++) {
                int row = warpM * 32 + mt * 16 + g;
                int cl = warpN * WN + nt * 8 + tc * 2;
                float b0 = bias[colBase + cl], b1 = bias[colBase + cl + 1];
                float* c = acc[mt][nt];
                tile[row * (BN + 1) + cl]           = fmaxf(c[0] + b0, 0.f);
                tile[row * (BN + 1) + cl + 1]       = fmaxf(c[1] + b1, 0.f);
                tile[(row + 8) * (BN + 1) + cl]     = fmaxf(c[2] + b0, 0.f);
                tile[(row + 8) * (BN + 1) + cl + 1] = fmaxf(c[3] + b1, 0.f);
            }
        }
        if (t < 128) pbs[t] = (rowBase + t < N) ? pb[rowBase + t] : -1;
        __syncthreads();

        constexpr int RPT = BN / 2;            // rows per thread (256 threads / BN cols)
        int cl = t % BN;
        int r0 = (t / BN) * RPT;
        float run = 0.0f;
        int cur = pbs[r0];
        #pragma unroll 4
        for (int r = r0; r < r0 + RPT; r++) {
            int sg = pbs[r];
            if (sg != cur) {
                if (cur >= 0 && run != 0.0f)
                    atomicAdd(&poolc[cur * 256 + colBase + cl], run);
                run = 0.0f;
                cur = sg;
            }
            if (sg >= 0) run += tile[r * (BN + 1) + cl];
        }
        if (cur >= 0 && run != 0.0f)
            atomicAdd(&poolc[cur * 256 + colBase + cl], run);
    }
}

// ---------------- feature pooling: per-segment fp32 sums ----------------
__global__ void featpool_kernel(const float* __restrict__ feature,
                                const int* __restrict__ segstart, float* __restrict__ poolf) {
    __shared__ float4 sh[16][16];
    int seg = blockIdx.x;
    int c = threadIdx.x % 16;
    int r = threadIdx.x / 16;
    int beg = segstart[seg], end = segstart[seg + 1];

    float4 acc = make_float4(0.f, 0.f, 0.f, 0.f);
    for (int i = beg + r; i < end; i += 16) {
        float4 v = *reinterpret_cast<const float4*>(&feature[(size_t)i * 64 + c * 4]);
        acc.x += v.x; acc.y += v.y; acc.z += v.z; acc.w += v.w;
    }
    sh[r][c] = acc;
    __syncthreads();
    for (int s = 8; s > 0; s >>= 1) {
        if (r < s) {
            float4 a = sh[r][c], b = sh[r + s][c];
            sh[r][c] = make_float4(a.x + b.x, a.y + b.y, a.z + b.z, a.w + b.w);
        }
        __syncthreads();
    }
    if (r == 0)
        *reinterpret_cast<float4*>(&poolf[seg * 64 + c * 4]) = sh[0][c];
}

// ---------------- MLP head ----------------
__global__ void fc1_kernel(const float* __restrict__ poolc, const float* __restrict__ poolf,
                           const int* __restrict__ segstart,
                           const float* __restrict__ Wf1, const float* __restrict__ bf1,
                           float* __restrict__ fc1) {
    __shared__ float srow[8][320];
    __shared__ float sinv[8];
    int rowBase = blockIdx.y * 8;
    int col = blockIdx.x * 256 + threadIdx.x;

    for (int lin = threadIdx.x; lin < 8 * 320; lin += 256) {
        int rr = lin / 320, k = lin % 320;
        int row = rowBase + rr;
        srow[rr][k] = (k < 256) ? poolc[row * 256 + k] : poolf[row * 64 + (k - 256)];
    }
    if (threadIdx.x < 8) {
        int row = rowBase + threadIdx.x;
        int c = segstart[row + 1] - segstart[row];
        sinv[threadIdx.x] = 1.0f / fmaxf((float)c, 1.0f);
    }
    __syncthreads();

    float acc[8] = {};
    #pragma unroll 4
    for (int k = 0; k < 320; k++) {
        float wv = Wf1[(size_t)k * 1024 + col];
        #pragma unroll
        for (int rr = 0; rr < 8; rr++) acc[rr] += srow[rr][k] * wv;
    }
    float b = bf1[col];
    #pragma unroll
    for (int rr = 0; rr < 8; rr++) {
        float v = acc[rr] * sinv[rr] + b;
        fc1[(size_t)(rowBase + rr) * 1024 + col] = fmaxf(v, 0.f);
    }
}

__global__ void fc2_kernel(const float* __restrict__ fc1, const float* __restrict__ Wf2,
                           const float* __restrict__ bf2, float* __restrict__ out) {
    int row = blockIdx.x;
    float a = 0.f;
    for (int j = threadIdx.x; j < 1024; j += 256)
        a += fc1[(size_t)row * 1024 + j] * Wf2[j];
    __shared__ float red[256];
    red[threadIdx.x] = a;
    __syncthreads();
    for (int s = 128; s > 0; s >>= 1) {
        if (threadIdx.x < s) red[threadIdx.x] += red[threadIdx.x + s];
        __syncthreads();
    }
    if (threadIdx.x == 0) out[row] = red[0] + bf2[0];
}

// ---------------- launch ----------------
extern "C" void kernel_launch(void* const* d_in, const int* in_sizes, int n_in,
                              void* d_out, int out_size) {
    const float* feature = (const float*)d_in[0];
    const int*   ei      = (const int*)d_in[1];
    const float* weight  = (const float*)d_in[2];
    const int*   pb      = (const int*)d_in[3];
    const float* W1 = (const float*)d_in[4];  const float* b1  = (const float*)d_in[5];
    const float* W2 = (const float*)d_in[6];  const float* b2  = (const float*)d_in[7];
    const float* W3 = (const float*)d_in[8];  const float* b3  = (const float*)d_in[9];
    const float* Wf1 = (const float*)d_in[10]; const float* bf1 = (const float*)d_in[11];
    const float* Wf2 = (const float*)d_in[12]; const float* bf2 = (const float*)d_in[13];
    float* out = (float*)d_out;

    int N = in_sizes[0] / 64;
    int E = in_sizes[2];
    const int* src = ei;
    const int* dst = ei + E;

    float *dinv, *poolc, *poolf, *fc1;
    __nv_bfloat16 *actb, *bufY, *featb, *whiT, *wloT;
    float2 *dc;
    int *rowptr, *woff, *bsums, *segstart;
    int2 *csr;
    cudaGetSymbolAddress((void**)&actb, g_actb);
    cudaGetSymbolAddress((void**)&bufY, g_bufY);
    cudaGetSymbolAddress((void**)&featb, g_featb);
    cudaGetSymbolAddress((void**)&dc, g_dc);
    cudaGetSymbolAddress((void**)&dinv, g_dinv);
    cudaGetSymbolAddress((void**)&rowptr, g_rowptr);
    cudaGetSymbolAddress((void**)&woff, g_woff);
    cudaGetSymbolAddress((void**)&bsums, g_bsums);
    cudaGetSymbolAddress((void**)&csr, g_csr);
    cudaGetSymbolAddress((void**)&segstart, g_segstart);
    cudaGetSymbolAddress((void**)&whiT, g_whiT);
    cudaGetSymbolAddress((void**)&wloT, g_wloT);
    cudaGetSymbolAddress((void**)&poolc, g_poolc);
    cudaGetSymbolAddress((void**)&poolf, g_poolf);
    cudaGetSymbolAddress((void**)&fc1,  g_fc1);

    // dynamic smem sizes: base(BN) = 20480 + BN*320; pool(BN=128) = 128*129*4 + 512
    const int SM_L1 = 20480 + 64 * 320;        // 40960
    const int SM_L2 = 20480 + 128 * 320;       // 61440
    const int SM_L3 = 128 * 129 * 4 + 512;     // 66560 (>= 61440 MMA need)
    cudaFuncSetAttribute(bf16_gemm_kernel<64, 64, 64, false>,
                         cudaFuncAttributeMaxDynamicSharedMemorySize, SM_L1);
    cudaFuncSetAttribute(bf16_gemm_kernel<128, 64, 128, false>,
                         cudaFuncAttributeMaxDynamicSharedMemorySize, SM_L2);
    cudaFuncSetAttribute(bf16_gemm_kernel<256, 128, 128, true>,
                         cudaFuncAttributeMaxDynamicSharedMemorySize, SM_L3);

    const int T = 256;
    int nb = (N + 1023) / 1024;
    int nWS = (45056 + 255) / 256;
    int nFC = (N * 16 + 255) / 256;
    int nDI = (N + 255) / 256;
    int nPZ = 256;   // zero 256*256 poolc

    // fused prep
    prep_kernel<<<nWS + nFC + 2 + nDI + nPZ, T>>>(W1, W2, W3, whiT, wloT, feature, featb,
                                                  pb, segstart, dc, poolc, N, nWS, nFC, nDI);
    deg_acc_kernel<<<(E + T - 1) / T, T>>>(dst, weight, dc, E);
    scan_block_kernel<<<nb, 1024>>>(dc, rowptr, bsums, dinv, N);
    add_off_kernel<<<(N + 1 + T - 1) / T, T>>>(rowptr, bsums, woff, N, E, nb);
    place_kernel<<<(E + T - 1) / T, T>>>(src, dst, weight, dinv, woff, csr, E);

    int gb128 = (N + 127) / 128;

    // layer 1: [N,64] -> [N,64]
    gather_kernel<64><<<(N * 8 + 255) / 256, 256>>>(rowptr, csr, featb, dinv, bufY, N);
    bf16_gemm_kernel<64, 64, 64, false><<<dim3(gb128, 1), 256, SM_L1>>>(
        bufY, whiT, wloT, b1, actb, nullptr, nullptr, N);

    // layer 2: [N,64] -> [N,128]  (single column tile: A loaded once)
    gather_kernel<64><<<(N * 8 + 255) / 256, 256>>>(rowptr, csr, actb, dinv, bufY, N);
    bf16_gemm_kernel<128, 64, 128, false><<<dim3(gb128, 1), 256, SM_L2>>>(
        bufY, whiT + 4096, wloT + 4096, b2, actb, nullptr, nullptr, N);

    // layer 3: [N,128] -> pooled segment sums directly (h3 never stored)
    gather_kernel<128><<<(N * 16 + 255) / 256, 256>>>(rowptr, csr, actb, dinv, bufY, N);
    bf16_gemm_kernel<256, 128, 128, true><<<dim3(gb128, 2), 256, SM_L3>>>(
        bufY, whiT + 12288, wloT + 12288, b3, nullptr, pb, poolc, N);

    // feature pooling (fp32 source) + MLP head
    featpool_kernel<<<256, 256>>>(feature, segstart, poolf);
    fc1_kernel<<<dim3(4, 32), 256>>>(poolc, poolf, segstart, Wf1, bf1, fc1);
    fc2_kernel<<<256, 256>>>(fc1, Wf2, bf2, out);
}